// round 17
// baseline (speedup 1.0000x reference)
#include <cuda_runtime.h>
#include <cuda_fp16.h>
#include <cuda_fp8.h>

#define FLAT 12288
#define HID  4096
#define NS   16
#define KST  4
#define LRf  0.01f
#define LRh  0.005f      // 0.5 * LR, folded into tanh-form sigmoid
#define RCH1 96          // 128-row chunks in fused conv pass
#define RCH2 192         // 64-row chunks in fp8 gemvT passes
#define WSCL 128.f       // fp8 storage scale (W*128); 1/128 folded into v/h
#define WINV (1.f / 128.f)
#define CTH  1024        // cheap-phase threads (single block)
#define VPT  (FLAT / CTH)   // 12 v-elements per thread (contiguous)
#define HPT  (HID / CTH)    // 4 h-elements per thread (contiguous)

// ---------------- device scratch (static, no runtime allocation) ----------------
__device__ unsigned char g_W8[(size_t)FLAT * HID];  // fp8 e4m3 copy of 128*W (48 MB)
__device__ float g_part[RCH2 * HID];  // gemvT partial column sums
__device__ float g_h[HID];            // dense-phase working h
__device__ float g_hA[HID];           // hinit_0 (q)
__device__ float g_hB[HID];           // hfinal_0 (s)
__device__ float g_vA[FLAT];          // vfinal_0 (r)

__device__ __forceinline__ float sigm(float x) { return 1.f / (1.f + __expf(-x)); }
__device__ __forceinline__ float tanha(float x) {
    float y;
    asm("tanh.approx.f32 %0, %1;" : "=f"(y) : "f"(x));
    return y;
}
// two sigmoids in one MUFU op (f16x2 tanh); for dot-only uses
__device__ __forceinline__ float2 sig2(float l0, float l1) {
    __half2 x = __floats2half2_rn(l0, l1);
    unsigned xi = *reinterpret_cast<unsigned*>(&x), yi;
    asm("tanh.approx.f16x2 %0, %1;" : "=r"(yi) : "r"(xi));
    __half2 th = *reinterpret_cast<__half2*>(&yi);
    __half2 H05 = __floats2half2_rn(0.5f, 0.5f);
    __half2 h = __hfma2(th, H05, H05);
    return __half22float2(h);
}
__device__ __forceinline__ __half2 fp8x2_to_h2(unsigned short s) {
    __half2_raw hr = __nv_cvt_fp8x2_to_halfraw2((__nv_fp8x2_storage_t)s, __NV_E4M3);
    return *reinterpret_cast<__half2*>(&hr);
}
__device__ __forceinline__ __half2 u2h2(unsigned u) {
    return *reinterpret_cast<__half2*>(&u);
}

// ---------------- dense phase: sample 0 (R16 winner, untouched) ----------------

__global__ void k_gemvT_conv(const float* __restrict__ W, const float* __restrict__ v) {
    __shared__ float sv[128];
    int r0 = blockIdx.y * 128;
    if (threadIdx.x < 128) sv[threadIdx.x] = v[r0 + threadIdx.x];
    __syncthreads();
    int col2 = blockIdx.x * 256 + threadIdx.x;
    const float2* Wp = (const float2*)W + (size_t)r0 * (HID / 2) + col2;
    unsigned short* W8p = (unsigned short*)g_W8 + (size_t)r0 * (HID / 2) + col2;
    float ax = 0.f, ay = 0.f;
#pragma unroll 8
    for (int r = 0; r < 128; r++) {
        float2 w = Wp[(size_t)r * (HID / 2)];
        float2 wsc; wsc.x = w.x * WSCL; wsc.y = w.y * WSCL;
        W8p[(size_t)r * (HID / 2)] =
            (unsigned short)__nv_cvt_float2_to_fp8x2(wsc, __NV_SATFINITE, __NV_E4M3);
        float s = sv[r];
        ax += w.x * s;
        ay += w.y * s;
    }
    float2 o; o.x = ax; o.y = ay;
    ((float2*)g_part)[blockIdx.y * (HID / 2) + col2] = o;
}

__global__ void k_gemvT(const float* __restrict__ v) {
    __shared__ __half2 sv2[64];
    int r0 = blockIdx.y * 64;
    if (threadIdx.x < 64) sv2[threadIdx.x] = __float2half2_rn(v[r0 + threadIdx.x] * WINV);
    __syncthreads();
    int col4 = blockIdx.x * 256 + threadIdx.x;
    const unsigned* Wp = (const unsigned*)g_W8 + (size_t)r0 * (HID / 4) + col4;
    __half2 acc0 = __float2half2_rn(0.f), acc1 = acc0;
#pragma unroll 8
    for (int r = 0; r < 64; r++) {
        unsigned w = Wp[(size_t)r * (HID / 4)];
        __half2 s2 = sv2[r];
        acc0 = __hfma2(fp8x2_to_h2((unsigned short)(w & 0xffffu)), s2, acc0);
        acc1 = __hfma2(fp8x2_to_h2((unsigned short)(w >> 16)), s2, acc1);
    }
    float2 f0 = __half22float2(acc0), f1 = __half22float2(acc1);
    float4 o; o.x = f0.x; o.y = f0.y; o.z = f1.x; o.w = f1.y;
    ((float4*)g_part)[blockIdx.y * (HID / 4) + col4] = o;
}

__global__ void k_hred(const float* __restrict__ b, int save, int nch) {
    int j = blockIdx.x * 256 + threadIdx.x;
    float s = b[j];
#pragma unroll 8
    for (int r = 0; r < nch; r++) s += g_part[r * HID + j];
    float h = sigm(s);
    g_h[j] = h;
    if (save == 1) g_hA[j] = h;
    else if (save == 2) g_hB[j] = h;
}

__global__ void k_gemv(const float* __restrict__ a) {
    __shared__ __half2 sh2[HID / 2];
    for (int k = threadIdx.x; k < HID / 2; k += blockDim.x)
        sh2[k] = __floats2half2_rn(g_h[2 * k] * WINV, g_h[2 * k + 1] * WINV);
    __syncthreads();
    int warp = threadIdx.x >> 5, lane = threadIdx.x & 31;
    int row = blockIdx.x * 16 + warp;
    const uint4* Wr = (const uint4*)(g_W8 + (size_t)row * HID);
    __half2 acc0 = __float2half2_rn(0.f), acc1 = acc0;
#pragma unroll 4
    for (int i = lane; i < HID / 16; i += 32) {
        uint4 wv = Wr[i];
        const uint4* hp = (const uint4*)&sh2[8 * i];
        uint4 h0 = hp[0], h1 = hp[1];
        acc0 = __hfma2(fp8x2_to_h2((unsigned short)(wv.x & 0xffffu)), u2h2(h0.x), acc0);
        acc1 = __hfma2(fp8x2_to_h2((unsigned short)(wv.x >> 16)),     u2h2(h0.y), acc1);
        acc0 = __hfma2(fp8x2_to_h2((unsigned short)(wv.y & 0xffffu)), u2h2(h0.z), acc0);
        acc1 = __hfma2(fp8x2_to_h2((unsigned short)(wv.y >> 16)),     u2h2(h0.w), acc1);
        acc0 = __hfma2(fp8x2_to_h2((unsigned short)(wv.z & 0xffffu)), u2h2(h1.x), acc0);
        acc1 = __hfma2(fp8x2_to_h2((unsigned short)(wv.z >> 16)),     u2h2(h1.y), acc1);
        acc0 = __hfma2(fp8x2_to_h2((unsigned short)(wv.w & 0xffffu)), u2h2(h1.z), acc0);
        acc1 = __hfma2(fp8x2_to_h2((unsigned short)(wv.w >> 16)),     u2h2(h1.w), acc1);
    }
    float2 r0 = __half22float2(acc0), r1 = __half22float2(acc1);
    float acc = (r0.x + r0.y) + (r1.x + r1.y);
#pragma unroll
    for (int o = 16; o; o >>= 1) acc += __shfl_down_sync(0xffffffffu, acc, o);
    if (lane == 0) g_vA[row] = sigm(a[row] + acc);
}

// ---------------- cheap phase: samples 1..15, rank-2 W, register-resident -----------
// MUFU-bound -> f16x2 tanh (2 sigmoids/MUFU) on dot-only phases; fp32 tanh on
// phases whose values are stored into carry state; exact expf on final out.
// Contiguous per-thread mapping: k = tid*VPT + kk -> float4 loads/stores.

__device__ __forceinline__ float2 blockdot2(float a, float b) {
    __shared__ float ra[32], rb[32], bc[2];
#pragma unroll
    for (int o = 16; o; o >>= 1) {
        a += __shfl_down_sync(0xffffffffu, a, o);
        b += __shfl_down_sync(0xffffffffu, b, o);
    }
    int w = threadIdx.x >> 5;
    if ((threadIdx.x & 31) == 0) { ra[w] = a; rb[w] = b; }
    __syncthreads();
    if (threadIdx.x < 32) {
        float x = ra[threadIdx.x], y = rb[threadIdx.x];
#pragma unroll
        for (int o = 16; o; o >>= 1) {
            x += __shfl_down_sync(0xffffffffu, x, o);
            y += __shfl_down_sync(0xffffffffu, y, o);
        }
        if (threadIdx.x == 0) { bc[0] = x; bc[1] = y; }
    }
    __syncthreads();
    float2 r; r.x = bc[0]; r.y = bc[1];
    return r;
}

__global__ void __launch_bounds__(CTH, 1) k_cheap(const float* __restrict__ inp,
                                                  float* __restrict__ out) {
    const int tid = threadIdx.x;
    const int kb = tid * VPT;      // contiguous v base
    const int jb = tid * HPT;      // contiguous h base
    float rq[HPT], rs[HPT], rqn[HPT], rsn[HPT], rr[VPT];

#pragma unroll
    for (int jj = 0; jj < HPT; jj += 4) {
        float4 q4 = *(const float4*)&g_hA[jb + jj];
        float4 s4 = *(const float4*)&g_hB[jb + jj];
        rq[jj] = q4.x; rq[jj+1] = q4.y; rq[jj+2] = q4.z; rq[jj+3] = q4.w;
        rs[jj] = s4.x; rs[jj+1] = s4.y; rs[jj+2] = s4.z; rs[jj+3] = s4.w;
    }
#pragma unroll
    for (int kk = 0; kk < VPT; kk += 4) {
        float4 v4 = *(const float4*)&g_vA[kb + kk];
        rr[kk] = v4.x; rr[kk+1] = v4.y; rr[kk+2] = v4.z; rr[kk+3] = v4.w;
    }

    float2 dv;
    {
        float a1 = 0.f, a2 = 0.f;
#pragma unroll
        for (int kk = 0; kk < VPT; kk += 4) {
            float4 x0 = *(const float4*)&inp[kb + kk];
            float4 x1 = *(const float4*)&inp[FLAT + kb + kk];
            a1 += x0.x * x1.x + x0.y * x1.y + x0.z * x1.z + x0.w * x1.w;
            a2 += rr[kk] * x1.x + rr[kk+1] * x1.y + rr[kk+2] * x1.z + rr[kk+3] * x1.w;
        }
        dv = blockdot2(a1, a2);
    }

#pragma unroll 1
    for (int i = 1; i < NS; i++) {
        const float* p  = inp + (size_t)(i - 1) * FLAT;
        const float* pn = inp + (size_t)i * FLAT;
        const float* xn = pn + FLAT;

#pragma unroll 1
        for (int t = 1; t <= KST; t++) {
            // ---- h phase ----
            float c1 = LRh * (1.f + dv.x), c2 = LRh * (1.f + dv.y);
            float a3 = 0.f, a4 = 0.f;
            if (t == 2 || t == 3) {
                // dot-only: f16x2 tanh
#pragma unroll
                for (int jj = 0; jj < HPT; jj += 2) {
                    float l0 = rq[jj] * c1 - rs[jj] * c2;
                    float l1 = rq[jj+1] * c1 - rs[jj+1] * c2;
                    float2 hf = sig2(l0, l1);
                    a3 += rq[jj] * hf.x + rq[jj+1] * hf.y;
                    a4 += rs[jj] * hf.x + rs[jj+1] * hf.y;
                }
            } else {
                // stored (t==1 -> q_next, t==KST -> s_next): fp32 tanh
#pragma unroll
                for (int jj = 0; jj < HPT; jj++) {
                    float h = fmaf(0.5f, tanha(rq[jj] * c1 - rs[jj] * c2), 0.5f);
                    if (t == 1) rqn[jj] = h;
                    else rsn[jj] = h;
                    a3 += rq[jj] * h;
                    a4 += rs[jj] * h;
                }
            }
            float2 dh = blockdot2(a3, a4);

            // ---- v phase ----
            float c3 = LRh * (1.f + dh.x), c4 = LRh * (1.f + dh.y);
            float a1 = 0.f, a2 = 0.f;
            if (t < KST) {
                // dot-only: f16x2 tanh, float4 p loads
#pragma unroll
                for (int kk = 0; kk < VPT; kk += 4) {
                    float4 p4 = *(const float4*)&p[kb + kk];
                    float l0 = p4.x * c3 - rr[kk] * c4;
                    float l1 = p4.y * c3 - rr[kk+1] * c4;
                    float2 f = sig2(l0, l1);
                    a1 += p4.x * f.x + p4.y * f.y;
                    a2 += rr[kk] * f.x + rr[kk+1] * f.y;
                    float l2 = p4.z * c3 - rr[kk+2] * c4;
                    float l3 = p4.w * c3 - rr[kk+3] * c4;
                    float2 g = sig2(l2, l3);
                    a1 += p4.z * g.x + p4.w * g.y;
                    a2 += rr[kk+2] * g.x + rr[kk+3] * g.y;
                }
            } else if (i < NS - 1) {
                // stored (v -> r): fp32 tanh
#pragma unroll
                for (int kk = 0; kk < VPT; kk += 4) {
                    float4 p4 = *(const float4*)&p[kb + kk];
                    float4 pn4 = *(const float4*)&pn[kb + kk];
                    float4 xn4 = *(const float4*)&xn[kb + kk];
                    float v0 = fmaf(0.5f, tanha(p4.x * c3 - rr[kk] * c4), 0.5f);
                    float v1 = fmaf(0.5f, tanha(p4.y * c3 - rr[kk+1] * c4), 0.5f);
                    float v2 = fmaf(0.5f, tanha(p4.z * c3 - rr[kk+2] * c4), 0.5f);
                    float v3 = fmaf(0.5f, tanha(p4.w * c3 - rr[kk+3] * c4), 0.5f);
                    rr[kk] = v0; rr[kk+1] = v1; rr[kk+2] = v2; rr[kk+3] = v3;
                    a1 += pn4.x * xn4.x + pn4.y * xn4.y + pn4.z * xn4.z + pn4.w * xn4.w;
                    a2 += v0 * xn4.x + v1 * xn4.y + v2 * xn4.z + v3 * xn4.w;
                }
            } else {
                // final reconstruction: exact sigmoid, float4 store
                float e3 = LRf * (1.f + dh.x), e4 = LRf * (1.f + dh.y);
#pragma unroll
                for (int kk = 0; kk < VPT; kk += 4) {
                    float4 p4 = *(const float4*)&p[kb + kk];
                    float4 o4;
                    o4.x = sigm(p4.x * e3 - rr[kk] * e4);
                    o4.y = sigm(p4.y * e3 - rr[kk+1] * e4);
                    o4.z = sigm(p4.z * e3 - rr[kk+2] * e4);
                    o4.w = sigm(p4.w * e3 - rr[kk+3] * e4);
                    *(float4*)&out[kb + kk] = o4;
                }
            }
            dv = blockdot2(a1, a2);
        }
#pragma unroll
        for (int jj = 0; jj < HPT; jj++) { rq[jj] = rqn[jj]; rs[jj] = rsn[jj]; }
    }
}

// ---------------- launch ----------------

extern "C" void kernel_launch(void* const* d_in, const int* in_sizes, int n_in,
                              void* d_out, int out_size) {
    const float* inp = (const float*)d_in[0];  // (16, 64, 64, 3) = 16 x 12288
    const float* W   = (const float*)d_in[1];  // (12288, 4096)
    const float* a   = (const float*)d_in[2];  // (12288, 1)
    const float* b   = (const float*)d_in[3];  // (4096, 1)
    float* out = (float*)d_out;                // (12288, 1)

    float* vA = 0;
    cudaGetSymbolAddress((void**)&vA, g_vA);

    for (int s = 0; s < KST; s++) {
        if (s == 0) {
            dim3 g1(HID / 512, RCH1);
            k_gemvT_conv<<<g1, 256>>>(W, inp);       // fused fp8 conversion
            k_hred<<<HID / 256, 256>>>(b, 1, RCH1);
        } else {
            dim3 g2(HID / 1024, RCH2);
            k_gemvT<<<g2, 256>>>(vA);
            k_hred<<<HID / 256, 256>>>(b, (s == KST - 1) ? 2 : 0, RCH2);
        }
        k_gemv<<<FLAT / 16, 512>>>(a);
    }
    k_cheap<<<1, CTH>>>(inp, out);
}